// round 1
// baseline (speedup 1.0000x reference)
#include <cuda_runtime.h>
#include <cuda_bf16.h>
#include <cstdint>

// ---------------- problem constants ----------------
#define MAX_NODES 50000
#define MAX_EDGES 800000
#define IN_DIM    128
#define HID       32
#define HEADS     4

// ---------------- scratch (device globals; no allocation allowed) ----------
__device__ int   g_is64;
__device__ int   g_src[MAX_EDGES];
__device__ int   g_dst[MAX_EDGES];

__device__ float g_q1[MAX_NODES * 128];
__device__ float g_k1[MAX_NODES * 128];
__device__ float g_v1[MAX_NODES * 128];
__device__ float g_aggr1[MAX_NODES * 128];   // starts as x@Ws1+bs1, edges accumulate

__device__ float g_p1[MAX_EDGES * 4];
__device__ float g_den1[MAX_NODES * 4];

__device__ float g_q2[MAX_NODES * 32];
__device__ float g_k2[MAX_NODES * 32];
__device__ float g_v2[MAX_NODES * 32];
__device__ float g_aggr2[MAX_NODES * 32];    // starts as h1@Ws2+bs2

__device__ float g_p2[MAX_EDGES];
__device__ float g_den2[MAX_NODES];

__device__ float g_colsum[32];

// ---------------- edge index handling ----------------
// If edge_index is int64 (little-endian, values < 50000) every odd int32 word
// is 0. If it is int32, odd words are random node ids (P[all 64 zero] ~ 0).
__global__ void detect_kernel(const int* __restrict__ ei) {
    if (threadIdx.x == 0 && blockIdx.x == 0) {
        int all_zero_hi = 1;
        for (int i = 0; i < 64; i++)
            if (ei[2 * i + 1] != 0) all_zero_hi = 0;
        g_is64 = all_zero_hi;
    }
}

__global__ void unpack_kernel(const void* __restrict__ ei, int E) {
    int e = blockIdx.x * blockDim.x + threadIdx.x;
    if (e >= E) return;
    if (g_is64) {
        const long long* p = (const long long*)ei;
        g_src[e] = (int)p[e];
        g_dst[e] = (int)p[E + e];
    } else {
        const int* p = (const int*)ei;
        g_src[e] = p[e];
        g_dst[e] = p[E + e];
    }
}

__global__ void zero_kernel(int n) {
    int i = blockIdx.x * blockDim.x + threadIdx.x;
    if (i < n * 4) g_den1[i] = 0.f;
    if (i < n)     g_den2[i] = 0.f;
    if (i < 32)    g_colsum[i] = 0.f;
}

// ---------------- SGEMM: out[M,N] = A[M,128] @ W[128,N] + bias ----------------
// K fixed at 128, BK = 32, BN == N (grid.y == 1).
template <int BM, int BN, int TM, int TN>
__global__ void sgemm_bias(const float* __restrict__ A,
                           const float* __restrict__ W,
                           const float* __restrict__ bias,
                           float* __restrict__ out,
                           int M, int N) {
    constexpr int BK = 32;
    constexpr int NT = (BM / TM) * (BN / TN);
    __shared__ float As[BM][BK + 1];
    __shared__ __align__(16) float Ws[BK][BN];

    const int tx = threadIdx.x % (BN / TN);
    const int ty = threadIdx.x / (BN / TN);
    const int row0 = blockIdx.x * BM;

    float acc[TM][TN];
#pragma unroll
    for (int i = 0; i < TM; i++)
#pragma unroll
        for (int j = 0; j < TN; j++) acc[i][j] = 0.f;

    for (int kt = 0; kt < 128; kt += BK) {
        for (int i = threadIdx.x; i < BM * BK; i += NT) {
            int r = i / BK, c = i % BK;
            int gr = row0 + r;
            As[r][c] = (gr < M) ? A[(size_t)gr * 128 + kt + c] : 0.f;
        }
        for (int i = threadIdx.x; i < BK * BN; i += NT) {
            int r = i / BN, c = i % BN;
            Ws[r][c] = W[(size_t)(kt + r) * N + c];
        }
        __syncthreads();
#pragma unroll
        for (int k = 0; k < BK; k++) {
            float ar[TM];
            float br[TN];
#pragma unroll
            for (int i = 0; i < TM; i++) ar[i] = As[ty * TM + i][k];
#pragma unroll
            for (int j = 0; j < TN; j += 4) {
                float4 b4 = *(const float4*)&Ws[k][tx * TN + j];
                br[j + 0] = b4.x; br[j + 1] = b4.y; br[j + 2] = b4.z; br[j + 3] = b4.w;
            }
#pragma unroll
            for (int i = 0; i < TM; i++)
#pragma unroll
                for (int j = 0; j < TN; j++) acc[i][j] += ar[i] * br[j];
        }
        __syncthreads();
    }

#pragma unroll
    for (int i = 0; i < TM; i++) {
        int gr = row0 + ty * TM + i;
        if (gr >= M) continue;
#pragma unroll
        for (int j = 0; j < TN; j++) {
            int gc = tx * TN + j;
            out[(size_t)gr * N + gc] = acc[i][j] + bias[gc];
        }
    }
}

// ---------------- layer 1 edge passes (HEADS=4, d=32) ----------------
__global__ void edge_logits1(const float* __restrict__ q,
                             const float* __restrict__ k, int E) {
    int idx = blockIdx.x * blockDim.x + threadIdx.x;
    if (idx >= E * 4) return;
    int e = idx >> 2, h = idx & 3;
    int s = g_src[e], d = g_dst[e];
    const float4* qp = (const float4*)(q + (size_t)d * 128 + h * 32);
    const float4* kp = (const float4*)(k + (size_t)s * 128 + h * 32);
    float dot = 0.f;
#pragma unroll
    for (int i = 0; i < 8; i++) {
        float4 a = qp[i], b = kp[i];
        dot += a.x * b.x + a.y * b.y + a.z * b.z + a.w * b.w;
    }
    float p = __expf(dot * 0.17677669529663689f);  // 1/sqrt(32)
    g_p1[idx] = p;
    atomicAdd(&g_den1[d * 4 + h], p);
}

__global__ void edge_scatter1(const float* __restrict__ v, int E) {
    int idx = blockIdx.x * blockDim.x + threadIdx.x;
    if (idx >= E * 32) return;
    int e = idx >> 5, j = idx & 31;   // j: which float4 of the 128-wide row
    int h = j >> 3;
    int s = g_src[e], d = g_dst[e];
    float alpha = g_p1[e * 4 + h] / g_den1[d * 4 + h];
    float4 val = ((const float4*)(v + (size_t)s * 128))[j];
    float* o = g_aggr1 + (size_t)d * 128 + j * 4;
    atomicAdd(o + 0, alpha * val.x);
    atomicAdd(o + 1, alpha * val.y);
    atomicAdd(o + 2, alpha * val.z);
    atomicAdd(o + 3, alpha * val.w);
}

// ---------------- layer 2 edge passes (1 head, d=32) ----------------
__global__ void edge_logits2(const float* __restrict__ q,
                             const float* __restrict__ k, int E) {
    int e = blockIdx.x * blockDim.x + threadIdx.x;
    if (e >= E) return;
    int s = g_src[e], d = g_dst[e];
    const float4* qp = (const float4*)(q + (size_t)d * 32);
    const float4* kp = (const float4*)(k + (size_t)s * 32);
    float dot = 0.f;
#pragma unroll
    for (int i = 0; i < 8; i++) {
        float4 a = qp[i], b = kp[i];
        dot += a.x * b.x + a.y * b.y + a.z * b.z + a.w * b.w;
    }
    float p = __expf(dot * 0.17677669529663689f);
    g_p2[e] = p;
    atomicAdd(&g_den2[d], p);
}

__global__ void edge_scatter2(const float* __restrict__ v, int E) {
    int idx = blockIdx.x * blockDim.x + threadIdx.x;
    if (idx >= E * 8) return;
    int e = idx >> 3, j = idx & 7;
    int s = g_src[e], d = g_dst[e];
    float alpha = g_p2[e] / g_den2[d];
    float4 val = ((const float4*)(v + (size_t)s * 32))[j];
    float* o = g_aggr2 + (size_t)d * 32 + j * 4;
    atomicAdd(o + 0, alpha * val.x);
    atomicAdd(o + 1, alpha * val.y);
    atomicAdd(o + 2, alpha * val.z);
    atomicAdd(o + 3, alpha * val.w);
}

// ---------------- misc ----------------
__global__ void relu_kernel(float* __restrict__ p, int n) {
    int i = blockIdx.x * blockDim.x + threadIdx.x;
    if (i < n) p[i] = fmaxf(p[i], 0.f);
}

__global__ void colsum_kernel(int n) {
    __shared__ float s[32];
    if (threadIdx.x < 32) s[threadIdx.x] = 0.f;
    __syncthreads();
    int warps_total = gridDim.x * (blockDim.x >> 5);
    int warp = (blockIdx.x * blockDim.x + threadIdx.x) >> 5;
    int lane = threadIdx.x & 31;
    float acc = 0.f;
    for (int r = warp; r < n; r += warps_total)
        acc += g_aggr2[(size_t)r * 32 + lane];
    atomicAdd(&s[lane], acc);
    __syncthreads();
    if (threadIdx.x < 32) atomicAdd(&g_colsum[threadIdx.x], s[threadIdx.x]);
}

__global__ void final_kernel(const float* __restrict__ Wo,
                             const float* __restrict__ bo,
                             float* __restrict__ out, int n) {
    float vv = 0.f;
    if (threadIdx.x < 32)
        vv = (g_colsum[threadIdx.x] / (float)n) * Wo[threadIdx.x];
#pragma unroll
    for (int o = 16; o; o >>= 1) vv += __shfl_down_sync(0xffffffffu, vv, o);
    if (threadIdx.x == 0) out[0] = vv + bo[0];
}

// ---------------- launch ----------------
extern "C" void kernel_launch(void* const* d_in, const int* in_sizes, int n_in,
                              void* d_out, int out_size) {
    const float* x   = (const float*)d_in[0];
    const void*  ei  = d_in[1];
    const float* Wq1 = (const float*)d_in[2];  const float* bq1 = (const float*)d_in[3];
    const float* Wk1 = (const float*)d_in[4];  const float* bk1 = (const float*)d_in[5];
    const float* Wv1 = (const float*)d_in[6];  const float* bv1 = (const float*)d_in[7];
    const float* Ws1 = (const float*)d_in[8];  const float* bs1 = (const float*)d_in[9];
    const float* Wq2 = (const float*)d_in[10]; const float* bq2 = (const float*)d_in[11];
    const float* Wk2 = (const float*)d_in[12]; const float* bk2 = (const float*)d_in[13];
    const float* Wv2 = (const float*)d_in[14]; const float* bv2 = (const float*)d_in[15];
    const float* Ws2 = (const float*)d_in[16]; const float* bs2 = (const float*)d_in[17];
    const float* Wo  = (const float*)d_in[18]; const float* bo  = (const float*)d_in[19];
    float* out = (float*)d_out;

    int n = in_sizes[0] / 128;
    int E = in_sizes[1] / 2;
    if (n > MAX_NODES) n = MAX_NODES;
    if (E > MAX_EDGES) E = MAX_EDGES;

    // device scratch pointers (symbol addresses; not an allocation)
    float *q1, *k1, *v1, *a1, *q2, *k2, *v2, *a2;
    cudaGetSymbolAddress((void**)&q1, g_q1);
    cudaGetSymbolAddress((void**)&k1, g_k1);
    cudaGetSymbolAddress((void**)&v1, g_v1);
    cudaGetSymbolAddress((void**)&a1, g_aggr1);
    cudaGetSymbolAddress((void**)&q2, g_q2);
    cudaGetSymbolAddress((void**)&k2, g_k2);
    cudaGetSymbolAddress((void**)&v2, g_v2);
    cudaGetSymbolAddress((void**)&a2, g_aggr2);

    detect_kernel<<<1, 32>>>((const int*)ei);
    unpack_kernel<<<(E + 255) / 256, 256>>>(ei, E);
    zero_kernel<<<(n * 4 + 255) / 256, 256>>>(n);

    // ---- layer 1 projections (128 -> 128 each) ----
    dim3 g1((n + 63) / 64);
    sgemm_bias<64, 128, 4, 8><<<g1, 256>>>(x, Wq1, bq1, q1, n, 128);
    sgemm_bias<64, 128, 4, 8><<<g1, 256>>>(x, Wk1, bk1, k1, n, 128);
    sgemm_bias<64, 128, 4, 8><<<g1, 256>>>(x, Wv1, bv1, v1, n, 128);
    sgemm_bias<64, 128, 4, 8><<<g1, 256>>>(x, Ws1, bs1, a1, n, 128);

    edge_logits1<<<(E * 4 + 255) / 256, 256>>>(q1, k1, E);
    edge_scatter1<<<(E * 32 + 255) / 256, 256>>>(v1, E);
    relu_kernel<<<(n * 128 + 255) / 256, 256>>>(a1, n * 128);

    // ---- layer 2 projections (128 -> 32 each), input = h1 (= a1) ----
    dim3 g2((n + 127) / 128);
    sgemm_bias<128, 32, 4, 4><<<g2, 256>>>(a1, Wq2, bq2, q2, n, 32);
    sgemm_bias<128, 32, 4, 4><<<g2, 256>>>(a1, Wk2, bk2, k2, n, 32);
    sgemm_bias<128, 32, 4, 4><<<g2, 256>>>(a1, Wv2, bv2, v2, n, 32);
    sgemm_bias<128, 32, 4, 4><<<g2, 256>>>(a1, Ws2, bs2, a2, n, 32);

    edge_logits2<<<(E + 255) / 256, 256>>>(q2, k2, E);
    edge_scatter2<<<(E * 8 + 255) / 256, 256>>>(v2, E);
    relu_kernel<<<(n * 32 + 255) / 256, 256>>>(a2, n * 32);

    colsum_kernel<<<256, 256>>>(n);
    final_kernel<<<1, 32>>>(Wo, bo, out, n);
}

// round 2
// speedup vs baseline: 1.9331x; 1.9331x over previous
#include <cuda_runtime.h>
#include <cuda_bf16.h>
#include <cstdint>

#define MAX_NODES 50000
#define MAX_EDGES 800000

// ---------------- device scratch ----------------
__device__ int   g_is64;
__device__ int   g_src[MAX_EDGES];
__device__ int   g_dst[MAX_EDGES];

__device__ int   g_deg[MAX_NODES + 1];
__device__ int   g_rowptr[MAX_NODES + 1];
__device__ int   g_cursor[MAX_NODES];
__device__ int   g_csr_src[MAX_EDGES];

__device__ float g_q1[MAX_NODES * 128];
__device__ float g_k1[MAX_NODES * 128];
__device__ float g_v1[MAX_NODES * 128];
__device__ float g_s1[MAX_NODES * 128];   // skip = x@Ws1+bs1
__device__ float g_h1[MAX_NODES * 128];   // layer-1 output

__device__ float g_q2[MAX_NODES * 32];
__device__ float g_k2[MAX_NODES * 32];
__device__ float g_v2[MAX_NODES * 32];
__device__ float g_s2[MAX_NODES * 32];
__device__ float g_h2[MAX_NODES * 32];

__device__ float g_colsum[32];

// ---------------- edge index handling ----------------
__global__ void detect_kernel(const int* __restrict__ ei) {
    if (threadIdx.x == 0 && blockIdx.x == 0) {
        int all_zero_hi = 1;
        for (int i = 0; i < 64; i++)
            if (ei[2 * i + 1] != 0) all_zero_hi = 0;
        g_is64 = all_zero_hi;
    }
}

__global__ void unpack_kernel(const void* __restrict__ ei, int E) {
    int e = blockIdx.x * blockDim.x + threadIdx.x;
    if (e >= E) return;
    if (g_is64) {
        const long long* p = (const long long*)ei;
        g_src[e] = (int)p[e];
        g_dst[e] = (int)p[E + e];
    } else {
        const int* p = (const int*)ei;
        g_src[e] = p[e];
        g_dst[e] = p[E + e];
    }
}

__global__ void zero_kernel(int n) {
    int i = blockIdx.x * blockDim.x + threadIdx.x;
    if (i <= n) g_deg[i] = 0;
    if (i < 32) g_colsum[i] = 0.f;
}

__global__ void hist_kernel(int E) {
    int e = blockIdx.x * blockDim.x + threadIdx.x;
    if (e < E) atomicAdd(&g_deg[g_dst[e]], 1);
}

// single-block exclusive scan of g_deg[0..n) -> g_rowptr / g_cursor
__global__ void scan_kernel(int n) {
    __shared__ int sums[32];
    __shared__ int s_carry;
    int t = threadIdx.x;
    if (t == 0) s_carry = 0;
    __syncthreads();
    int nchunks = (n + 1023) / 1024;
    for (int c = 0; c < nchunks; c++) {
        int idx = c * 1024 + t;
        int val = (idx < n) ? g_deg[idx] : 0;
        // warp inclusive scan
        int x = val;
        #pragma unroll
        for (int o = 1; o < 32; o <<= 1) {
            int y = __shfl_up_sync(0xffffffffu, x, o);
            if ((t & 31) >= o) x += y;
        }
        if ((t & 31) == 31) sums[t >> 5] = x;
        __syncthreads();
        if (t < 32) {
            int s = sums[t];
            int xs = s;
            #pragma unroll
            for (int o = 1; o < 32; o <<= 1) {
                int y = __shfl_up_sync(0xffffffffu, xs, o);
                if (t >= o) xs += y;
            }
            sums[t] = xs - s;  // exclusive
        }
        __syncthreads();
        int incl = x + sums[t >> 5];
        int excl = incl - val;
        int carry = s_carry;
        if (idx < n) {
            g_rowptr[idx] = carry + excl;
            g_cursor[idx] = carry + excl;
        }
        __syncthreads();
        if (t == 1023) s_carry = carry + incl;
        __syncthreads();
    }
    if (t == 0) g_rowptr[n] = s_carry;
}

__global__ void fill_kernel(int E) {
    int e = blockIdx.x * blockDim.x + threadIdx.x;
    if (e >= E) return;
    int d = g_dst[e];
    int pos = atomicAdd(&g_cursor[d], 1);
    g_csr_src[pos] = g_src[e];
}

// ---------------- fused 4-way GEMM, layer 1: [M,128] x 4x[128,128] ----------------
// BM=64, 256 threads, TM=4, TN=8. A block held in smem for all 4 W.
__global__ __launch_bounds__(256) void gemm4_l1(
    const float* __restrict__ A,
    const float* __restrict__ W0, const float* __restrict__ W1,
    const float* __restrict__ W2, const float* __restrict__ W3,
    const float* __restrict__ b0, const float* __restrict__ b1,
    const float* __restrict__ b2, const float* __restrict__ b3,
    float* __restrict__ o0, float* __restrict__ o1,
    float* __restrict__ o2, float* __restrict__ o3, int M)
{
    __shared__ float As[64][128];   // 32KB
    __shared__ float Ws[32][128];   // 16KB
    int t = threadIdx.x;
    int tx = t % 16, ty = t / 16;   // col = tx*8, row = ty*4
    int row0 = blockIdx.x * 64;

    for (int i = t; i < 64 * 32; i += 256) {
        int r = i / 32, c4 = i % 32;
        float4 val = make_float4(0.f, 0.f, 0.f, 0.f);
        if (row0 + r < M)
            val = *(const float4*)&A[(size_t)(row0 + r) * 128 + c4 * 4];
        *(float4*)&As[r][c4 * 4] = val;
    }

    const float* Wl[4] = {W0, W1, W2, W3};
    const float* bl[4] = {b0, b1, b2, b3};
    float* ol[4] = {o0, o1, o2, o3};

    for (int w = 0; w < 4; w++) {
        float acc[4][8];
        #pragma unroll
        for (int i = 0; i < 4; i++)
            #pragma unroll
            for (int j = 0; j < 8; j++) acc[i][j] = 0.f;

        const float* W = Wl[w];
        for (int kt = 0; kt < 128; kt += 32) {
            __syncthreads();
            for (int i = t; i < 32 * 32; i += 256) {
                int r = i / 32, c4 = i % 32;
                *(float4*)&Ws[r][c4 * 4] =
                    *(const float4*)&W[(size_t)(kt + r) * 128 + c4 * 4];
            }
            __syncthreads();
            #pragma unroll 8
            for (int k = 0; k < 32; k++) {
                float ar[4];
                #pragma unroll
                for (int i = 0; i < 4; i++) ar[i] = As[ty * 4 + i][kt + k];
                float4 wa = *(const float4*)&Ws[k][tx * 8];
                float4 wb = *(const float4*)&Ws[k][tx * 8 + 4];
                #pragma unroll
                for (int i = 0; i < 4; i++) {
                    acc[i][0] += ar[i] * wa.x; acc[i][1] += ar[i] * wa.y;
                    acc[i][2] += ar[i] * wa.z; acc[i][3] += ar[i] * wa.w;
                    acc[i][4] += ar[i] * wb.x; acc[i][5] += ar[i] * wb.y;
                    acc[i][6] += ar[i] * wb.z; acc[i][7] += ar[i] * wb.w;
                }
            }
        }
        float4 ba = *(const float4*)&bl[w][tx * 8];
        float4 bb = *(const float4*)&bl[w][tx * 8 + 4];
        #pragma unroll
        for (int i = 0; i < 4; i++) {
            int r = row0 + ty * 4 + i;
            if (r >= M) continue;
            float4 oa = make_float4(acc[i][0] + ba.x, acc[i][1] + ba.y,
                                    acc[i][2] + ba.z, acc[i][3] + ba.w);
            float4 ob = make_float4(acc[i][4] + bb.x, acc[i][5] + bb.y,
                                    acc[i][6] + bb.z, acc[i][7] + bb.w);
            *(float4*)&ol[w][(size_t)r * 128 + tx * 8] = oa;
            *(float4*)&ol[w][(size_t)r * 128 + tx * 8 + 4] = ob;
        }
    }
}

// ---------------- fused 4-way GEMM, layer 2: [M,128] x 4x[128,32] ----------------
// BM=64, 256 threads; all 4 W tiles in smem simultaneously. TM=2, TN=4.
__global__ __launch_bounds__(256) void gemm4_l2(
    const float* __restrict__ A,
    const float* __restrict__ W0, const float* __restrict__ W1,
    const float* __restrict__ W2, const float* __restrict__ W3,
    const float* __restrict__ b0, const float* __restrict__ b1,
    const float* __restrict__ b2, const float* __restrict__ b3,
    float* __restrict__ o0, float* __restrict__ o1,
    float* __restrict__ o2, float* __restrict__ o3, int M)
{
    __shared__ float As[64][128];      // 32KB
    __shared__ float Ws[4][32][32];    // 16KB
    int t = threadIdx.x;
    int tx = t % 8, ty = t / 8;        // col = tx*4, row = ty*2
    int row0 = blockIdx.x * 64;

    for (int i = t; i < 64 * 32; i += 256) {
        int r = i / 32, c4 = i % 32;
        float4 val = make_float4(0.f, 0.f, 0.f, 0.f);
        if (row0 + r < M)
            val = *(const float4*)&A[(size_t)(row0 + r) * 128 + c4 * 4];
        *(float4*)&As[r][c4 * 4] = val;
    }

    const float* Wl[4] = {W0, W1, W2, W3};
    const float* bl[4] = {b0, b1, b2, b3};
    float* ol[4] = {o0, o1, o2, o3};

    float acc[4][2][4];
    #pragma unroll
    for (int w = 0; w < 4; w++)
        #pragma unroll
        for (int i = 0; i < 2; i++)
            #pragma unroll
            for (int j = 0; j < 4; j++) acc[w][i][j] = 0.f;

    for (int kt = 0; kt < 128; kt += 32) {
        __syncthreads();
        for (int i = t; i < 4 * 32 * 8; i += 256) {
            int w = i / 256, rem = i % 256;
            int r = rem / 8, c4 = rem % 8;
            *(float4*)&Ws[w][r][c4 * 4] =
                *(const float4*)&Wl[w][(size_t)(kt + r) * 32 + c4 * 4];
        }
        __syncthreads();
        #pragma unroll 8
        for (int k = 0; k < 32; k++) {
            float a0 = As[ty * 2][kt + k];
            float a1 = As[ty * 2 + 1][kt + k];
            #pragma unroll
            for (int w = 0; w < 4; w++) {
                float4 wv = *(const float4*)&Ws[w][k][tx * 4];
                acc[w][0][0] += a0 * wv.x; acc[w][0][1] += a0 * wv.y;
                acc[w][0][2] += a0 * wv.z; acc[w][0][3] += a0 * wv.w;
                acc[w][1][0] += a1 * wv.x; acc[w][1][1] += a1 * wv.y;
                acc[w][1][2] += a1 * wv.z; acc[w][1][3] += a1 * wv.w;
            }
        }
    }
    #pragma unroll
    for (int w = 0; w < 4; w++) {
        float4 bv = *(const float4*)&bl[w][tx * 4];
        #pragma unroll
        for (int i = 0; i < 2; i++) {
            int r = row0 + ty * 2 + i;
            if (r >= M) continue;
            float4 ov = make_float4(acc[w][i][0] + bv.x, acc[w][i][1] + bv.y,
                                    acc[w][i][2] + bv.z, acc[w][i][3] + bv.w);
            *(float4*)&ol[w][(size_t)r * 32 + tx * 4] = ov;
        }
    }
}

// ---------------- fused edge attention, layer 1 (4 heads x 32) ----------------
// one warp per dst node; lane l owns dims [4l,4l+4); head = l/8
__global__ void edge_attn1(const float* __restrict__ q,
                           const float* __restrict__ k,
                           const float* __restrict__ v,
                           const float* __restrict__ skip,
                           float* __restrict__ h, int n)
{
    int warp = (blockIdx.x * blockDim.x + threadIdx.x) >> 5;
    int lane = threadIdx.x & 31;
    if (warp >= n) return;
    int i = warp;

    float4 q4 = *(const float4*)&q[(size_t)i * 128 + lane * 4];
    float4 acc = make_float4(0.f, 0.f, 0.f, 0.f);
    float den = 0.f;
    int beg = g_rowptr[i], end = g_rowptr[i + 1];

    for (int e = beg; e < end; e++) {
        int s = g_csr_src[e];
        float4 k4 = *(const float4*)&k[(size_t)s * 128 + lane * 4];
        float4 v4 = *(const float4*)&v[(size_t)s * 128 + lane * 4];
        float d = q4.x * k4.x + q4.y * k4.y + q4.z * k4.z + q4.w * k4.w;
        d += __shfl_xor_sync(0xffffffffu, d, 1);
        d += __shfl_xor_sync(0xffffffffu, d, 2);
        d += __shfl_xor_sync(0xffffffffu, d, 4);   // head-local (8-lane) dot
        float p = __expf(d * 0.17677669529663689f);
        den += p;
        acc.x += p * v4.x; acc.y += p * v4.y;
        acc.z += p * v4.z; acc.w += p * v4.w;
    }
    float inv = (den > 0.f) ? (1.f / den) : 0.f;
    float4 sk = *(const float4*)&skip[(size_t)i * 128 + lane * 4];
    float4 o = make_float4(fmaxf(sk.x + acc.x * inv, 0.f),
                           fmaxf(sk.y + acc.y * inv, 0.f),
                           fmaxf(sk.z + acc.z * inv, 0.f),
                           fmaxf(sk.w + acc.w * inv, 0.f));
    *(float4*)&h[(size_t)i * 128 + lane * 4] = o;
}

// ---------------- fused edge attention, layer 2 (1 head x 32) ----------------
// 8-lane group per dst node (4 nodes per warp)
__global__ void edge_attn2(const float* __restrict__ q,
                           const float* __restrict__ k,
                           const float* __restrict__ v,
                           const float* __restrict__ skip,
                           float* __restrict__ h, int n)
{
    int tid = blockIdx.x * blockDim.x + threadIdx.x;
    int node = tid >> 3;
    if (node >= n) return;
    int m = threadIdx.x & 7;
    unsigned mask = 0xFFu << ((threadIdx.x & 31) & ~7);

    float4 q4 = *(const float4*)&q[(size_t)node * 32 + m * 4];
    float4 acc = make_float4(0.f, 0.f, 0.f, 0.f);
    float den = 0.f;
    int beg = g_rowptr[node], end = g_rowptr[node + 1];

    for (int e = beg; e < end; e++) {
        int s = g_csr_src[e];
        float4 k4 = *(const float4*)&k[(size_t)s * 32 + m * 4];
        float4 v4 = *(const float4*)&v[(size_t)s * 32 + m * 4];
        float d = q4.x * k4.x + q4.y * k4.y + q4.z * k4.z + q4.w * k4.w;
        d += __shfl_xor_sync(mask, d, 1);
        d += __shfl_xor_sync(mask, d, 2);
        d += __shfl_xor_sync(mask, d, 4);
        float p = __expf(d * 0.17677669529663689f);
        den += p;
        acc.x += p * v4.x; acc.y += p * v4.y;
        acc.z += p * v4.z; acc.w += p * v4.w;
    }
    float inv = (den > 0.f) ? (1.f / den) : 0.f;
    float4 sk = *(const float4*)&skip[(size_t)node * 32 + m * 4];
    float4 o = make_float4(fmaxf(sk.x + acc.x * inv, 0.f),
                           fmaxf(sk.y + acc.y * inv, 0.f),
                           fmaxf(sk.z + acc.z * inv, 0.f),
                           fmaxf(sk.w + acc.w * inv, 0.f));
    *(float4*)&h[(size_t)node * 32 + m * 4] = o;
}

// ---------------- reduction ----------------
__global__ void colsum_kernel(int n) {
    __shared__ float s[32];
    if (threadIdx.x < 32) s[threadIdx.x] = 0.f;
    __syncthreads();
    int warps_total = gridDim.x * (blockDim.x >> 5);
    int warp = (blockIdx.x * blockDim.x + threadIdx.x) >> 5;
    int lane = threadIdx.x & 31;
    float acc = 0.f;
    for (int r = warp; r < n; r += warps_total)
        acc += g_h2[(size_t)r * 32 + lane];
    atomicAdd(&s[lane], acc);
    __syncthreads();
    if (threadIdx.x < 32) atomicAdd(&g_colsum[threadIdx.x], s[threadIdx.x]);
}

__global__ void final_kernel(const float* __restrict__ Wo,
                             const float* __restrict__ bo,
                             float* __restrict__ out, int n) {
    float vv = 0.f;
    if (threadIdx.x < 32)
        vv = (g_colsum[threadIdx.x] / (float)n) * Wo[threadIdx.x];
    #pragma unroll
    for (int o = 16; o; o >>= 1) vv += __shfl_down_sync(0xffffffffu, vv, o);
    if (threadIdx.x == 0) out[0] = vv + bo[0];
}

// ---------------- launch ----------------
extern "C" void kernel_launch(void* const* d_in, const int* in_sizes, int n_in,
                              void* d_out, int out_size) {
    const float* x   = (const float*)d_in[0];
    const void*  ei  = d_in[1];
    const float* Wq1 = (const float*)d_in[2];  const float* bq1 = (const float*)d_in[3];
    const float* Wk1 = (const float*)d_in[4];  const float* bk1 = (const float*)d_in[5];
    const float* Wv1 = (const float*)d_in[6];  const float* bv1 = (const float*)d_in[7];
    const float* Ws1 = (const float*)d_in[8];  const float* bs1 = (const float*)d_in[9];
    const float* Wq2 = (const float*)d_in[10]; const float* bq2 = (const float*)d_in[11];
    const float* Wk2 = (const float*)d_in[12]; const float* bk2 = (const float*)d_in[13];
    const float* Wv2 = (const float*)d_in[14]; const float* bv2 = (const float*)d_in[15];
    const float* Ws2 = (const float*)d_in[16]; const float* bs2 = (const float*)d_in[17];
    const float* Wo  = (const float*)d_in[18]; const float* bo  = (const float*)d_in[19];
    float* out = (float*)d_out;

    int n = in_sizes[0] / 128;
    int E = in_sizes[1] / 2;
    if (n > MAX_NODES) n = MAX_NODES;
    if (E > MAX_EDGES) E = MAX_EDGES;

    float *q1, *k1, *v1, *s1, *h1, *q2, *k2, *v2, *s2, *h2;
    cudaGetSymbolAddress((void**)&q1, g_q1);
    cudaGetSymbolAddress((void**)&k1, g_k1);
    cudaGetSymbolAddress((void**)&v1, g_v1);
    cudaGetSymbolAddress((void**)&s1, g_s1);
    cudaGetSymbolAddress((void**)&h1, g_h1);
    cudaGetSymbolAddress((void**)&q2, g_q2);
    cudaGetSymbolAddress((void**)&k2, g_k2);
    cudaGetSymbolAddress((void**)&v2, g_v2);
    cudaGetSymbolAddress((void**)&s2, g_s2);
    cudaGetSymbolAddress((void**)&h2, g_h2);

    detect_kernel<<<1, 32>>>((const int*)ei);
    unpack_kernel<<<(E + 255) / 256, 256>>>(ei, E);
    zero_kernel<<<(n + 256) / 256, 256>>>(n);
    hist_kernel<<<(E + 255) / 256, 256>>>(E);
    scan_kernel<<<1, 1024>>>(n);
    fill_kernel<<<(E + 255) / 256, 256>>>(E);

    int gb = (n + 63) / 64;
    gemm4_l1<<<gb, 256>>>(x, Wq1, Wk1, Wv1, Ws1, bq1, bk1, bv1, bs1,
                          q1, k1, v1, s1, n);
    edge_attn1<<<(n * 32 + 255) / 256, 256>>>(q1, k1, v1, s1, h1, n);

    gemm4_l2<<<gb, 256>>>(h1, Wq2, Wk2, Wv2, Ws2, bq2, bk2, bv2, bs2,
                          q2, k2, v2, s2, n);
    edge_attn2<<<(n * 8 + 255) / 256, 256>>>(q2, k2, v2, s2, h2, n);

    colsum_kernel<<<256, 256>>>(n);
    final_kernel<<<1, 32>>>(Wo, bo, out, n);
}

// round 3
// speedup vs baseline: 2.6133x; 1.3518x over previous
#include <cuda_runtime.h>
#include <cuda_bf16.h>
#include <cstdint>

#define MAX_NODES 50000
#define MAX_EDGES 800000

// ---------------- device scratch ----------------
__device__ int   g_is64;
__device__ int   g_src[MAX_EDGES];
__device__ int   g_dst[MAX_EDGES];

__device__ int   g_deg[MAX_NODES + 1];
__device__ int   g_rowptr[MAX_NODES + 1];
__device__ int   g_cursor[MAX_NODES];
__device__ int   g_csr_src[MAX_EDGES];

// layer 1: q/k/v in bf16 (packed bf162), skip & h in fp32
__device__ __nv_bfloat162 g_q1b[MAX_NODES * 64];
__device__ __nv_bfloat162 g_k1b[MAX_NODES * 64];
__device__ __nv_bfloat162 g_v1b[MAX_NODES * 64];
__device__ float g_s1[MAX_NODES * 128];
__device__ float g_h1[MAX_NODES * 128];

// layer 2
__device__ __nv_bfloat162 g_q2b[MAX_NODES * 16];
__device__ __nv_bfloat162 g_k2b[MAX_NODES * 16];
__device__ __nv_bfloat162 g_v2b[MAX_NODES * 16];
__device__ float g_s2[MAX_NODES * 32];
__device__ float g_h2[MAX_NODES * 32];

__device__ float g_colsum[32];

// ---------------- helpers ----------------
__device__ __forceinline__ unsigned pack_bf2(float a, float b) {
    __nv_bfloat162 h = __floats2bfloat162_rn(a, b);
    return *(unsigned*)&h;
}
__device__ __forceinline__ float2 unpack_bf2(unsigned u) {
    __nv_bfloat162 h = *(__nv_bfloat162*)&u;
    return __bfloat1622float2(h);
}

// ---------------- edge index handling ----------------
__global__ void detect_kernel(const int* __restrict__ ei) {
    if (threadIdx.x == 0 && blockIdx.x == 0) {
        int all_zero_hi = 1;
        for (int i = 0; i < 64; i++)
            if (ei[2 * i + 1] != 0) all_zero_hi = 0;
        g_is64 = all_zero_hi;
    }
}

__global__ void zero_kernel(int n) {
    int i = blockIdx.x * blockDim.x + threadIdx.x;
    if (i <= n) g_deg[i] = 0;
    if (i < 32) g_colsum[i] = 0.f;
}

// unpack + degree histogram in one pass
__global__ void unpack_hist_kernel(const void* __restrict__ ei, int E) {
    int e = blockIdx.x * blockDim.x + threadIdx.x;
    if (e >= E) return;
    int s, d;
    if (g_is64) {
        const long long* p = (const long long*)ei;
        s = (int)p[e];
        d = (int)p[E + e];
    } else {
        const int* p = (const int*)ei;
        s = p[e];
        d = p[E + e];
    }
    g_src[e] = s;
    g_dst[e] = d;
    atomicAdd(&g_deg[d], 1);
}

// single-block exclusive scan of g_deg[0..n) -> g_rowptr / g_cursor
__global__ void scan_kernel(int n) {
    __shared__ int sums[32];
    __shared__ int s_carry;
    int t = threadIdx.x;
    if (t == 0) s_carry = 0;
    __syncthreads();
    int nchunks = (n + 1023) / 1024;
    for (int c = 0; c < nchunks; c++) {
        int idx = c * 1024 + t;
        int val = (idx < n) ? g_deg[idx] : 0;
        int x = val;
        #pragma unroll
        for (int o = 1; o < 32; o <<= 1) {
            int y = __shfl_up_sync(0xffffffffu, x, o);
            if ((t & 31) >= o) x += y;
        }
        if ((t & 31) == 31) sums[t >> 5] = x;
        __syncthreads();
        if (t < 32) {
            int s = sums[t];
            int xs = s;
            #pragma unroll
            for (int o = 1; o < 32; o <<= 1) {
                int y = __shfl_up_sync(0xffffffffu, xs, o);
                if (t >= o) xs += y;
            }
            sums[t] = xs - s;
        }
        __syncthreads();
        int incl = x + sums[t >> 5];
        int excl = incl - val;
        int carry = s_carry;
        if (idx < n) {
            g_rowptr[idx] = carry + excl;
            g_cursor[idx] = carry + excl;
        }
        __syncthreads();
        if (t == 1023) s_carry = carry + incl;
        __syncthreads();
    }
    if (t == 0) g_rowptr[n] = s_carry;
}

__global__ void fill_kernel(int E) {
    int e = blockIdx.x * blockDim.x + threadIdx.x;
    if (e >= E) return;
    int d = g_dst[e];
    int pos = atomicAdd(&g_cursor[d], 1);
    g_csr_src[pos] = g_src[e];
}

// ---------------- GEMM layer 1: A[M,128] x 4x W[128,128] ----------------
// BM=128, 256 threads, TM=8 x TN=(4+4 split at +64). A transposed in smem,
// loaded once; W staged per 64-k chunk. q/k/v out bf16, s out fp32.
__global__ __launch_bounds__(256, 2) void gemm_l1(
    const float* __restrict__ A,
    const float* __restrict__ W0, const float* __restrict__ W1,
    const float* __restrict__ W2, const float* __restrict__ W3,
    const float* __restrict__ b0, const float* __restrict__ b1,
    const float* __restrict__ b2, const float* __restrict__ b3,
    __nv_bfloat162* __restrict__ oq, __nv_bfloat162* __restrict__ ok,
    __nv_bfloat162* __restrict__ ov, float* __restrict__ os, int M)
{
    extern __shared__ float sm[];
    float* AsT = sm;                 // [128][129]  (k-major, transposed)
    float* Wst = sm + 128 * 129;     // [64][128]

    int t = threadIdx.x;
    int tx = t & 15, ty = t >> 4;    // tx: col group, ty: row group (0..15)
    int row0 = blockIdx.x * 128;

    // stage A transposed (coalesced global read, 4-way conflicted smem store - one time)
    for (int i = t; i < 128 * 32; i += 256) {
        int r = i >> 5, c4 = i & 31;
        float4 v = make_float4(0.f, 0.f, 0.f, 0.f);
        if (row0 + r < M) v = *(const float4*)&A[(size_t)(row0 + r) * 128 + c4 * 4];
        AsT[(c4 * 4 + 0) * 129 + r] = v.x;
        AsT[(c4 * 4 + 1) * 129 + r] = v.y;
        AsT[(c4 * 4 + 2) * 129 + r] = v.z;
        AsT[(c4 * 4 + 3) * 129 + r] = v.w;
    }

    const float* Wl[4] = {W0, W1, W2, W3};
    const float* bl[4] = {b0, b1, b2, b3};

    for (int w = 0; w < 4; w++) {
        float acc[8][8];
        #pragma unroll
        for (int i = 0; i < 8; i++)
            #pragma unroll
            for (int j = 0; j < 8; j++) acc[i][j] = 0.f;

        const float* W = Wl[w];
        for (int kc = 0; kc < 2; kc++) {
            __syncthreads();
            for (int i = t; i < 64 * 32; i += 256) {
                int r = i >> 5, c4 = i & 31;
                *(float4*)&Wst[r * 128 + c4 * 4] =
                    *(const float4*)&W[(size_t)(kc * 64 + r) * 128 + c4 * 4];
            }
            __syncthreads();
            int kb = kc * 64;
            #pragma unroll 8
            for (int k = 0; k < 64; k++) {
                const float* arow = &AsT[(kb + k) * 129 + ty * 8];
                float4 w0 = *(const float4*)&Wst[k * 128 + tx * 4];
                float4 w1 = *(const float4*)&Wst[k * 128 + tx * 4 + 64];
                #pragma unroll
                for (int i = 0; i < 8; i++) {
                    float a = arow[i];
                    acc[i][0] += a * w0.x; acc[i][1] += a * w0.y;
                    acc[i][2] += a * w0.z; acc[i][3] += a * w0.w;
                    acc[i][4] += a * w1.x; acc[i][5] += a * w1.y;
                    acc[i][6] += a * w1.z; acc[i][7] += a * w1.w;
                }
            }
        }
        // epilogue
        float4 ba = *(const float4*)&bl[w][tx * 4];
        float4 bb = *(const float4*)&bl[w][tx * 4 + 64];
        if (w < 3) {
            __nv_bfloat162* o = (w == 0) ? oq : (w == 1) ? ok : ov;
            #pragma unroll
            for (int i = 0; i < 8; i++) {
                int r = row0 + ty * 8 + i;
                if (r >= M) continue;
                uint2 ua, ub;
                ua.x = pack_bf2(acc[i][0] + ba.x, acc[i][1] + ba.y);
                ua.y = pack_bf2(acc[i][2] + ba.z, acc[i][3] + ba.w);
                ub.x = pack_bf2(acc[i][4] + bb.x, acc[i][5] + bb.y);
                ub.y = pack_bf2(acc[i][6] + bb.z, acc[i][7] + bb.w);
                *(uint2*)&o[(size_t)r * 64 + tx * 2] = ua;
                *(uint2*)&o[(size_t)r * 64 + 32 + tx * 2] = ub;
            }
        } else {
            #pragma unroll
            for (int i = 0; i < 8; i++) {
                int r = row0 + ty * 8 + i;
                if (r >= M) continue;
                float4 fa = make_float4(acc[i][0] + ba.x, acc[i][1] + ba.y,
                                        acc[i][2] + ba.z, acc[i][3] + ba.w);
                float4 fb = make_float4(acc[i][4] + bb.x, acc[i][5] + bb.y,
                                        acc[i][6] + bb.z, acc[i][7] + bb.w);
                *(float4*)&os[(size_t)r * 128 + tx * 4] = fa;
                *(float4*)&os[(size_t)r * 128 + tx * 4 + 64] = fb;
            }
        }
    }
}

// ---------------- GEMM layer 2: A[M,128] x concat(4x W[128,32]) = N=128 ----
__global__ __launch_bounds__(256, 2) void gemm_l2(
    const float* __restrict__ A,
    const float* __restrict__ W0, const float* __restrict__ W1,
    const float* __restrict__ W2, const float* __restrict__ W3,
    const float* __restrict__ b0, const float* __restrict__ b1,
    const float* __restrict__ b2, const float* __restrict__ b3,
    __nv_bfloat162* __restrict__ oq, __nv_bfloat162* __restrict__ ok,
    __nv_bfloat162* __restrict__ ov, float* __restrict__ os, int M)
{
    extern __shared__ float sm[];
    float* AsT = sm;
    float* Wst = sm + 128 * 129;

    int t = threadIdx.x;
    int tx = t & 15, ty = t >> 4;
    int row0 = blockIdx.x * 128;

    for (int i = t; i < 128 * 32; i += 256) {
        int r = i >> 5, c4 = i & 31;
        float4 v = make_float4(0.f, 0.f, 0.f, 0.f);
        if (row0 + r < M) v = *(const float4*)&A[(size_t)(row0 + r) * 128 + c4 * 4];
        AsT[(c4 * 4 + 0) * 129 + r] = v.x;
        AsT[(c4 * 4 + 1) * 129 + r] = v.y;
        AsT[(c4 * 4 + 2) * 129 + r] = v.z;
        AsT[(c4 * 4 + 3) * 129 + r] = v.w;
    }

    const float* Wl[4] = {W0, W1, W2, W3};

    float acc[8][8];
    #pragma unroll
    for (int i = 0; i < 8; i++)
        #pragma unroll
        for (int j = 0; j < 8; j++) acc[i][j] = 0.f;

    for (int kc = 0; kc < 2; kc++) {
        __syncthreads();
        for (int i = t; i < 64 * 32; i += 256) {
            int r = i >> 5, c4 = i & 31;
            int w = c4 >> 3, cc = (c4 & 7) * 4;
            *(float4*)&Wst[r * 128 + c4 * 4] =
                *(const float4*)&Wl[w][(size_t)(kc * 64 + r) * 32 + cc];
        }
        __syncthreads();
        int kb = kc * 64;
        #pragma unroll 8
        for (int k = 0; k < 64; k++) {
            const float* arow = &AsT[(kb + k) * 129 + ty * 8];
            float4 w0 = *(const float4*)&Wst[k * 128 + tx * 4];
            float4 w1 = *(const float4*)&Wst[k * 128 + tx * 4 + 64];
            #pragma unroll
            for (int i = 0; i < 8; i++) {
                float a = arow[i];
                acc[i][0] += a * w0.x; acc[i][1] += a * w0.y;
                acc[i][2] += a * w0.z; acc[i][3] += a * w0.w;
                acc[i][4] += a * w1.x; acc[i][5] += a * w1.y;
                acc[i][6] += a * w1.z; acc[i][7] += a * w1.w;
            }
        }
    }

    // epilogue: cols tx*4 (w0i in {0,1}) and tx*4+64 (w1i in {2,3})
    int w0i = tx >> 3;            // 0 -> q, 1 -> k
    int w1i = 2 + (tx >> 3);      // 2 -> v, 3 -> s
    int lc = (tx * 4) & 31;       // local col within the [128,32] matrix
    const float* blo[4] = {b0, b1, b2, b3};
    float4 ba = *(const float4*)&blo[w0i][lc];
    float4 bb = *(const float4*)&blo[w1i][lc];
    __nv_bfloat162* oA = (w0i == 0) ? oq : ok;

    #pragma unroll
    for (int i = 0; i < 8; i++) {
        int r = row0 + ty * 8 + i;
        if (r >= M) continue;
        uint2 ua;
        ua.x = pack_bf2(acc[i][0] + ba.x, acc[i][1] + ba.y);
        ua.y = pack_bf2(acc[i][2] + ba.z, acc[i][3] + ba.w);
        *(uint2*)&oA[(size_t)r * 16 + (lc >> 1)] = ua;
        if (w1i == 2) {
            uint2 ub;
            ub.x = pack_bf2(acc[i][4] + bb.x, acc[i][5] + bb.y);
            ub.y = pack_bf2(acc[i][6] + bb.z, acc[i][7] + bb.w);
            *(uint2*)&ov[(size_t)r * 16 + (lc >> 1)] = ub;
        } else {
            float4 fb = make_float4(acc[i][4] + bb.x, acc[i][5] + bb.y,
                                    acc[i][6] + bb.z, acc[i][7] + bb.w);
            *(float4*)&os[(size_t)r * 32 + lc] = fb;
        }
    }
}

// ---------------- fused edge attention, layer 1 (4 heads x 32, bf16 q/k/v) ----
__global__ void edge_attn1(const __nv_bfloat162* __restrict__ q,
                           const __nv_bfloat162* __restrict__ k,
                           const __nv_bfloat162* __restrict__ v,
                           const float* __restrict__ skip,
                           float* __restrict__ h, int n)
{
    int warp = (blockIdx.x * blockDim.x + threadIdx.x) >> 5;
    int lane = threadIdx.x & 31;
    if (warp >= n) return;
    int node = warp;

    const uint2* qp = (const uint2*)q;
    const uint2* kp = (const uint2*)k;
    const uint2* vp = (const uint2*)v;

    uint2 qu = qp[(size_t)node * 32 + lane];
    float2 q01 = unpack_bf2(qu.x), q23 = unpack_bf2(qu.y);

    float4 acc = make_float4(0.f, 0.f, 0.f, 0.f);
    float den = 0.f;
    int beg = g_rowptr[node], end = g_rowptr[node + 1];

    for (int e = beg; e < end; e++) {
        int s = g_csr_src[e];
        uint2 ku = kp[(size_t)s * 32 + lane];
        uint2 vu = vp[(size_t)s * 32 + lane];
        float2 k01 = unpack_bf2(ku.x), k23 = unpack_bf2(ku.y);
        float2 v01 = unpack_bf2(vu.x), v23 = unpack_bf2(vu.y);
        float d = q01.x * k01.x + q01.y * k01.y + q23.x * k23.x + q23.y * k23.y;
        d += __shfl_xor_sync(0xffffffffu, d, 1);
        d += __shfl_xor_sync(0xffffffffu, d, 2);
        d += __shfl_xor_sync(0xffffffffu, d, 4);   // 8-lane (head-local) dot
        float p = __expf(d * 0.17677669529663689f);
        den += p;
        acc.x += p * v01.x; acc.y += p * v01.y;
        acc.z += p * v23.x; acc.w += p * v23.y;
    }
    float inv = (den > 0.f) ? (1.f / den) : 0.f;
    float4 sk = *(const float4*)&skip[(size_t)node * 128 + lane * 4];
    float4 o = make_float4(fmaxf(sk.x + acc.x * inv, 0.f),
                           fmaxf(sk.y + acc.y * inv, 0.f),
                           fmaxf(sk.z + acc.z * inv, 0.f),
                           fmaxf(sk.w + acc.w * inv, 0.f));
    *(float4*)&h[(size_t)node * 128 + lane * 4] = o;
}

// ---------------- fused edge attention, layer 2 (1 head x 32, bf16) ----------
__global__ void edge_attn2(const __nv_bfloat162* __restrict__ q,
                           const __nv_bfloat162* __restrict__ k,
                           const __nv_bfloat162* __restrict__ v,
                           const float* __restrict__ skip,
                           float* __restrict__ h, int n)
{
    int tid = blockIdx.x * blockDim.x + threadIdx.x;
    int node = tid >> 3;
    if (node >= n) return;
    int m = threadIdx.x & 7;
    unsigned mask = 0xFFu << ((threadIdx.x & 31) & ~7);

    const uint2* qp = (const uint2*)q;
    const uint2* kp = (const uint2*)k;
    const uint2* vp = (const uint2*)v;

    uint2 qu = qp[(size_t)node * 8 + m];
    float2 q01 = unpack_bf2(qu.x), q23 = unpack_bf2(qu.y);

    float4 acc = make_float4(0.f, 0.f, 0.f, 0.f);
    float den = 0.f;
    int beg = g_rowptr[node], end = g_rowptr[node + 1];

    for (int e = beg; e < end; e++) {
        int s = g_csr_src[e];
        uint2 ku = kp[(size_t)s * 8 + m];
        uint2 vu = vp[(size_t)s * 8 + m];
        float2 k01 = unpack_bf2(ku.x), k23 = unpack_bf2(ku.y);
        float2 v01 = unpack_bf2(vu.x), v23 = unpack_bf2(vu.y);
        float d = q01.x * k01.x + q01.y * k01.y + q23.x * k23.x + q23.y * k23.y;
        d += __shfl_xor_sync(mask, d, 1);
        d += __shfl_xor_sync(mask, d, 2);
        d += __shfl_xor_sync(mask, d, 4);
        float p = __expf(d * 0.17677669529663689f);
        den += p;
        acc.x += p * v01.x; acc.y += p * v01.y;
        acc.z += p * v23.x; acc.w += p * v23.y;
    }
    float inv = (den > 0.f) ? (1.f / den) : 0.f;
    float4 sk = *(const float4*)&skip[(size_t)node * 32 + m * 4];
    float4 o = make_float4(fmaxf(sk.x + acc.x * inv, 0.f),
                           fmaxf(sk.y + acc.y * inv, 0.f),
                           fmaxf(sk.z + acc.z * inv, 0.f),
                           fmaxf(sk.w + acc.w * inv, 0.f));
    *(float4*)&h[(size_t)node * 32 + m * 4] = o;
}

// ---------------- reduction ----------------
__global__ void colsum_kernel(int n) {
    __shared__ float s[32];
    if (threadIdx.x < 32) s[threadIdx.x] = 0.f;
    __syncthreads();
    int warps_total = gridDim.x * (blockDim.x >> 5);
    int warp = (blockIdx.x * blockDim.x + threadIdx.x) >> 5;
    int lane = threadIdx.x & 31;
    float acc = 0.f;
    for (int r = warp; r < n; r += warps_total)
        acc += g_h2[(size_t)r * 32 + lane];
    atomicAdd(&s[lane], acc);
    __syncthreads();
    if (threadIdx.x < 32) atomicAdd(&g_colsum[threadIdx.x], s[threadIdx.x]);
}

__global__ void final_kernel(const float* __restrict__ Wo,
                             const float* __restrict__ bo,
                             float* __restrict__ out, int n) {
    float vv = 0.f;
    if (threadIdx.x < 32)
        vv = (g_colsum[threadIdx.x] / (float)n) * Wo[threadIdx.x];
    #pragma unroll
    for (int o = 16; o; o >>= 1) vv += __shfl_down_sync(0xffffffffu, vv, o);
    if (threadIdx.x == 0) out[0] = vv + bo[0];
}

// ---------------- launch ----------------
extern "C" void kernel_launch(void* const* d_in, const int* in_sizes, int n_in,
                              void* d_out, int out_size) {
    const float* x   = (const float*)d_in[0];
    const void*  ei  = d_in[1];
    const float* Wq1 = (const float*)d_in[2];  const float* bq1 = (const float*)d_in[3];
    const float* Wk1 = (const float*)d_in[4];  const float* bk1 = (const float*)d_in[5];
    const float* Wv1 = (const float*)d_in[6];  const float* bv1 = (const float*)d_in[7];
    const float* Ws1 = (const float*)d_in[8];  const float* bs1 = (const float*)d_in[9];
    const float* Wq2 = (const float*)d_in[10]; const float* bq2 = (const float*)d_in[11];
    const float* Wk2 = (const float*)d_in[12]; const float* bk2 = (const float*)d_in[13];
    const float* Wv2 = (const float*)d_in[14]; const float* bv2 = (const float*)d_in[15];
    const float* Ws2 = (const float*)d_in[16]; const float* bs2 = (const float*)d_in[17];
    const float* Wo  = (const float*)d_in[18]; const float* bo  = (const float*)d_in[19];
    float* out = (float*)d_out;

    int n = in_sizes[0] / 128;
    int E = in_sizes[1] / 2;
    if (n > MAX_NODES) n = MAX_NODES;
    if (E > MAX_EDGES) E = MAX_EDGES;

    __nv_bfloat162 *q1b, *k1b, *v1b, *q2b, *k2b, *v2b;
    float *s1, *h1, *s2, *h2;
    cudaGetSymbolAddress((void**)&q1b, g_q1b);
    cudaGetSymbolAddress((void**)&k1b, g_k1b);
    cudaGetSymbolAddress((void**)&v1b, g_v1b);
    cudaGetSymbolAddress((void**)&s1,  g_s1);
    cudaGetSymbolAddress((void**)&h1,  g_h1);
    cudaGetSymbolAddress((void**)&q2b, g_q2b);
    cudaGetSymbolAddress((void**)&k2b, g_k2b);
    cudaGetSymbolAddress((void**)&v2b, g_v2b);
    cudaGetSymbolAddress((void**)&s2,  g_s2);
    cudaGetSymbolAddress((void**)&h2,  g_h2);

    const int SMEM = (128 * 129 + 64 * 128) * 4;   // 98816 B
    cudaFuncSetAttribute(gemm_l1, cudaFuncAttributeMaxDynamicSharedMemorySize, SMEM);
    cudaFuncSetAttribute(gemm_l2, cudaFuncAttributeMaxDynamicSharedMemorySize, SMEM);

    detect_kernel<<<1, 32>>>((const int*)ei);
    zero_kernel<<<(n + 256) / 256, 256>>>(n);
    unpack_hist_kernel<<<(E + 255) / 256, 256>>>(ei, E);
    scan_kernel<<<1, 1024>>>(n);
    fill_kernel<<<(E + 255) / 256, 256>>>(E);

    int gb = (n + 127) / 128;
    gemm_l1<<<gb, 256, SMEM>>>(x, Wq1, Wk1, Wv1, Ws1, bq1, bk1, bv1, bs1,
                               q1b, k1b, v1b, s1, n);
    edge_attn1<<<(n * 32 + 255) / 256, 256>>>(q1b, k1b, v1b, s1, h1, n);

    gemm_l2<<<gb, 256, SMEM>>>(h1, Wq2, Wk2, Wv2, Ws2, bq2, bk2, bv2, bs2,
                               q2b, k2b, v2b, s2, n);
    edge_attn2<<<(n * 8 + 255) / 256, 256>>>(q2b, k2b, v2b, s2, h2, n);

    colsum_kernel<<<256, 256>>>(n);
    final_kernel<<<1, 32>>>(Wo, bo, out, n);
}

// round 5
// speedup vs baseline: 3.6173x; 1.3842x over previous
#include <cuda_runtime.h>
#include <cuda_bf16.h>
#include <cstdint>

#define MAX_NODES 50000
#define MAX_EDGES 800000
#define SA 132        // A smem row stride (floats): banks 4r+c -> conflict-free
#define SB 136        // W smem row stride (floats): banks 8t+g -> conflict-free

// ---------------- device scratch ----------------
__device__ int   g_is64;
__device__ int   g_src[MAX_EDGES];
__device__ int   g_dst[MAX_EDGES];

__device__ int   g_deg[MAX_NODES + 1];
__device__ int   g_rowptr[MAX_NODES + 1];
__device__ int   g_cursor[MAX_NODES];
__device__ int   g_csr_src[MAX_EDGES];
__device__ int   g_bsum[64];
__device__ int   g_boff[64];

// layer 1: q/k/v packed bf16 (validated OK); skip & h1 fp32 (precision-critical)
__device__ unsigned g_q1b[MAX_NODES * 64];
__device__ unsigned g_k1b[MAX_NODES * 64];
__device__ unsigned g_v1b[MAX_NODES * 64];
__device__ float    g_s1[MAX_NODES * 128];
__device__ float    g_h1[MAX_NODES * 128];

// layer 2
__device__ unsigned g_q2b[MAX_NODES * 16];
__device__ unsigned g_k2b[MAX_NODES * 16];
__device__ unsigned g_v2b[MAX_NODES * 16];
__device__ float    g_s2[MAX_NODES * 32];

__device__ float g_part[((MAX_NODES + 31) / 32) * 32];

// ---------------- helpers ----------------
__device__ __forceinline__ unsigned pack_bf2(float a, float b) {
    __nv_bfloat162 h = __floats2bfloat162_rn(a, b);
    return *(unsigned*)&h;
}
__device__ __forceinline__ float2 unpack_bf2(unsigned u) {
    __nv_bfloat162 h = *(__nv_bfloat162*)&u;
    return __bfloat1622float2(h);
}
__device__ __forceinline__ float f2tf(float f) {
    unsigned u;
    asm("cvt.rna.tf32.f32 %0, %1;" : "=r"(u) : "f"(f));
    return __uint_as_float(u);
}
__device__ __forceinline__ void mma_tf32(float* c, const unsigned* a, const unsigned* b) {
    asm volatile("mma.sync.aligned.m16n8k8.row.col.f32.tf32.tf32.f32 "
                 "{%0,%1,%2,%3}, {%4,%5,%6,%7}, {%8,%9}, {%0,%1,%2,%3};"
                 : "+f"(c[0]), "+f"(c[1]), "+f"(c[2]), "+f"(c[3])
                 : "r"(a[0]), "r"(a[1]), "r"(a[2]), "r"(a[3]), "r"(b[0]), "r"(b[1]));
}

// ---------------- init / edge preprocessing ----------------
__global__ void init_kernel(const int* __restrict__ ei, int n) {
    int i = blockIdx.x * blockDim.x + threadIdx.x;
    if (i == 0) {
        int all_zero_hi = 1;
        for (int j = 0; j < 64; j++)
            if (ei[2 * j + 1] != 0) all_zero_hi = 0;
        g_is64 = all_zero_hi;
    }
    if (i <= n) g_deg[i] = 0;
}

__global__ void unpack_hist_kernel(const void* __restrict__ ei, int E) {
    int e = blockIdx.x * blockDim.x + threadIdx.x;
    if (e >= E) return;
    int s, d;
    if (g_is64) {
        const long long* p = (const long long*)ei;
        s = (int)p[e];
        d = (int)p[E + e];
    } else {
        const int* p = (const int*)ei;
        s = p[e];
        d = p[E + e];
    }
    g_src[e] = s;
    g_dst[e] = d;
    atomicAdd(&g_deg[d], 1);
}

__global__ void scan_phase1(int n) {
    __shared__ int wsum[8];
    __shared__ int woff[8];
    int t = threadIdx.x, lane = t & 31, warp = t >> 5;
    int base = blockIdx.x * 2048 + t * 8;
    int v[8], s = 0;
    #pragma unroll
    for (int i = 0; i < 8; i++) {
        int idx = base + i;
        int x = (idx < n) ? g_deg[idx] : 0;
        v[i] = s;
        s += x;
    }
    int x = s;
    #pragma unroll
    for (int o = 1; o < 32; o <<= 1) {
        int y = __shfl_up_sync(0xffffffffu, x, o);
        if (lane >= o) x += y;
    }
    if (lane == 31) wsum[warp] = x;
    __syncthreads();
    if (t == 0) {
        int run = 0;
        #pragma unroll
        for (int j = 0; j < 8; j++) { int tmp = wsum[j]; woff[j] = run; run += tmp; }
        g_bsum[blockIdx.x] = run;
    }
    __syncthreads();
    int off = woff[warp] + (x - s);
    #pragma unroll
    for (int i = 0; i < 8; i++) {
        int idx = base + i;
        if (idx < n) g_rowptr[idx] = off + v[i];
    }
}

__global__ void scan_phase2(int nb, int n) {
    int t = threadIdx.x;
    int v = (t < nb) ? g_bsum[t] : 0;
    int x = v;
    #pragma unroll
    for (int o = 1; o < 32; o <<= 1) {
        int y = __shfl_up_sync(0xffffffffu, x, o);
        if (t >= o) x += y;
    }
    if (t < nb) g_boff[t] = x - v;
    if (t == 31) g_rowptr[n] = x;
}

__global__ void scan_phase3(int n) {
    int idx = blockIdx.x * blockDim.x + threadIdx.x;
    if (idx >= n) return;
    int val = g_rowptr[idx] + g_boff[idx >> 11];
    g_rowptr[idx] = val;
    g_cursor[idx] = val;
}

__global__ void fill_kernel(int E) {
    int e = blockIdx.x * blockDim.x + threadIdx.x;
    if (e >= E) return;
    int d = g_dst[e];
    int pos = atomicAdd(&g_cursor[d], 1);
    g_csr_src[pos] = g_src[e];
}

// ---------------- tf32 mma chunk: warp tile 32(m) x 64(n), 64 k-rows ------
__device__ __forceinline__ void mma_chunk(const float* As, const float* Ws,
                                          int kbase, int warp_m, int warp_n,
                                          int lane, float c[2][8][4]) {
    int gid = lane >> 2, tig = lane & 3;
    const float* ab = &As[(warp_m * 32 + gid) * SA];
    #pragma unroll
    for (int kk = 0; kk < 8; kk++) {
        int kc0 = kbase + kk * 8 + tig;
        int wr = kk * 8 + tig;
        unsigned a0[4], a1[4];
        a0[0] = __float_as_uint(ab[kc0]);
        a0[1] = __float_as_uint(ab[8 * SA + kc0]);
        a0[2] = __float_as_uint(ab[kc0 + 4]);
        a0[3] = __float_as_uint(ab[8 * SA + kc0 + 4]);
        a1[0] = __float_as_uint(ab[16 * SA + kc0]);
        a1[1] = __float_as_uint(ab[24 * SA + kc0]);
        a1[2] = __float_as_uint(ab[16 * SA + kc0 + 4]);
        a1[3] = __float_as_uint(ab[24 * SA + kc0 + 4]);
        #pragma unroll
        for (int nt = 0; nt < 8; nt++) {
            unsigned b[2];
            int col = warp_n * 64 + nt * 8 + gid;
            b[0] = __float_as_uint(Ws[wr * SB + col]);
            b[1] = __float_as_uint(Ws[(wr + 4) * SB + col]);
            mma_tf32(c[0][nt], a0, b);
            mma_tf32(c[1][nt], a1, b);
        }
    }
}

// ---------------- GEMM layer 1: tf32 MMA, A[M,128] x 4 x W[128,128] -------
__global__ __launch_bounds__(256, 2) void gemm_l1(
    const float* __restrict__ A,
    const float* __restrict__ W0, const float* __restrict__ W1,
    const float* __restrict__ W2, const float* __restrict__ W3,
    const float* __restrict__ b0, const float* __restrict__ b1,
    const float* __restrict__ b2, const float* __restrict__ b3,
    unsigned* __restrict__ oq, unsigned* __restrict__ okk,
    unsigned* __restrict__ ov, float* __restrict__ os, int M)
{
    extern __shared__ float smf[];
    float* As = smf;                 // 128 x SA
    float* Ws = smf + 128 * SA;      // 64  x SB

    int t = threadIdx.x, lane = t & 31, wid = t >> 5;
    int warp_m = wid & 3, warp_n = wid >> 2;
    int row0 = blockIdx.x * 128;

    // stage A once (fp32 -> tf32)
    for (int i = t; i < 128 * 32; i += 256) {
        int r = i >> 5, c4 = i & 31;
        float4 v = make_float4(0.f, 0.f, 0.f, 0.f);
        if (row0 + r < M) v = *(const float4*)&A[(size_t)(row0 + r) * 128 + c4 * 4];
        *(float4*)&As[r * SA + c4 * 4] =
            make_float4(f2tf(v.x), f2tf(v.y), f2tf(v.z), f2tf(v.w));
    }

    const float* Wl[4] = {W0, W1, W2, W3};
    const float* bl[4] = {b0, b1, b2, b3};
    unsigned* ol[3] = {oq, okk, ov};

    for (int w = 0; w < 4; w++) {
        float c[2][8][4];
        #pragma unroll
        for (int i = 0; i < 2; i++)
            #pragma unroll
            for (int j = 0; j < 8; j++)
                #pragma unroll
                for (int q = 0; q < 4; q++) c[i][j][q] = 0.f;

        const float* W = Wl[w];
        for (int kc = 0; kc < 2; kc++) {
            __syncthreads();
            for (int i = t; i < 64 * 32; i += 256) {
                int r = i >> 5, c4 = i & 31;
                float4 v = *(const float4*)&W[(size_t)(kc * 64 + r) * 128 + c4 * 4];
                *(float4*)&Ws[r * SB + c4 * 4] =
                    make_float4(f2tf(v.x), f2tf(v.y), f2tf(v.z), f2tf(v.w));
            }
            __syncthreads();
            mma_chunk(As, Ws, kc * 64, warp_m, warp_n, lane, c);
        }

        #pragma unroll
        for (int mt = 0; mt < 2; mt++) {
            #pragma unroll
            for (int nt = 0; nt < 8; nt++) {
                int rg = row0 + warp_m * 32 + mt * 16 + (lane >> 2);
                int col = warp_n * 64 + nt * 8 + (lane & 3) * 2;
                float2 bb = *(const float2*)&bl[w][col];
                float x0 = c[mt][nt][0] + bb.x, x1 = c[mt][nt][1] + bb.y;
                float x2 = c[mt][nt][2] + bb.x, x3 = c[mt][nt][3] + bb.y;
                if (w < 3) {
                    if (rg < M)     ol[w][(size_t)rg * 64 + (col >> 1)] = pack_bf2(x0, x1);
                    if (rg + 8 < M) ol[w][(size_t)(rg + 8) * 64 + (col >> 1)] = pack_bf2(x2, x3);
                } else {
                    if (rg < M)     *(float2*)&os[(size_t)rg * 128 + col] = make_float2(x0, x1);
                    if (rg + 8 < M) *(float2*)&os[(size_t)(rg + 8) * 128 + col] = make_float2(x2, x3);
                }
            }
        }
    }
}

// ---------------- GEMM layer 2: A(h1 fp32)[M,128] x concat(4 x W[128,32]) --
__global__ __launch_bounds__(256, 2) void gemm_l2(
    const float* __restrict__ A,
    const float* __restrict__ W0, const float* __restrict__ W1,
    const float* __restrict__ W2, const float* __restrict__ W3,
    const float* __restrict__ b0, const float* __restrict__ b1,
    const float* __restrict__ b2, const float* __restrict__ b3,
    unsigned* __restrict__ oq, unsigned* __restrict__ okk,
    unsigned* __restrict__ ov, float* __restrict__ os, int M)
{
    extern __shared__ float smf[];
    float* As = smf;
    float* Ws = smf + 128 * SA;

    int t = threadIdx.x, lane = t & 31, wid = t >> 5;
    int warp_m = wid & 3, warp_n = wid >> 2;
    int row0 = blockIdx.x * 128;

    for (int i = t; i < 128 * 32; i += 256) {
        int r = i >> 5, c4 = i & 31;
        float4 v = make_float4(0.f, 0.f, 0.f, 0.f);
        if (row0 + r < M) v = *(const float4*)&A[(size_t)(row0 + r) * 128 + c4 * 4];
        *(float4*)&As[r * SA + c4 * 4] =
            make_float4(f2tf(v.x), f2tf(v.y), f2tf(v.z), f2tf(v.w));
    }

    const float* Wl[4] = {W0, W1, W2, W3};
    const float* bl[4] = {b0, b1, b2, b3};

    float c[2][8][4];
    #pragma unroll
    for (int i = 0; i < 2; i++)
        #pragma unroll
        for (int j = 0; j < 8; j++)
            #pragma unroll
            for (int q = 0; q < 4; q++) c[i][j][q] = 0.f;

    for (int kc = 0; kc < 2; kc++) {
        __syncthreads();
        // Wcat: global col = mat*32 + lc; stage rows kc*64..kc*64+63
        for (int i = t; i < 64 * 64; i += 256) {
            int r = i >> 6, cp = i & 63;
            int col = cp * 2, w = col >> 5, lc = col & 31;
            float2 f = *(const float2*)&Wl[w][(size_t)(kc * 64 + r) * 32 + lc];
            Ws[r * SB + col]     = f2tf(f.x);
            Ws[r * SB + col + 1] = f2tf(f.y);
        }
        __syncthreads();
        mma_chunk(As, Ws, kc * 64, warp_m, warp_n, lane, c);
    }

    #pragma unroll
    for (int mt = 0; mt < 2; mt++) {
        #pragma unroll
        for (int nt = 0; nt < 8; nt++) {
            int rg = row0 + warp_m * 32 + mt * 16 + (lane >> 2);
            int col = warp_n * 64 + nt * 8 + (lane & 3) * 2;
            int mat = col >> 5, lc = col & 31;
            float2 bb = *(const float2*)&bl[mat][lc];
            float x0 = c[mt][nt][0] + bb.x, x1 = c[mt][nt][1] + bb.y;
            float x2 = c[mt][nt][2] + bb.x, x3 = c[mt][nt][3] + bb.y;
            if (mat < 3) {
                unsigned* o = (mat == 0) ? oq : (mat == 1) ? okk : ov;
                if (rg < M)     o[(size_t)rg * 16 + (lc >> 1)] = pack_bf2(x0, x1);
                if (rg + 8 < M) o[(size_t)(rg + 8) * 16 + (lc >> 1)] = pack_bf2(x2, x3);
            } else {
                if (rg < M)     *(float2*)&os[(size_t)rg * 32 + lc] = make_float2(x0, x1);
                if (rg + 8 < M) *(float2*)&os[(size_t)(rg + 8) * 32 + lc] = make_float2(x2, x3);
            }
        }
    }
}

// ---------------- fused edge attention, layer 1 (4 heads x 32) -------------
__global__ void edge_attn1(const unsigned* __restrict__ q,
                           const unsigned* __restrict__ k,
                           const unsigned* __restrict__ v,
                           const float* __restrict__ skip,
                           float* __restrict__ h, int n)
{
    int warp = (blockIdx.x * blockDim.x + threadIdx.x) >> 5;
    int lane = threadIdx.x & 31;
    if (warp >= n) return;
    int node = warp;

    const uint2* qp = (const uint2*)q;
    const uint2* kp = (const uint2*)k;
    const uint2* vp = (const uint2*)v;

    uint2 qu = qp[(size_t)node * 32 + lane];
    float2 q01 = unpack_bf2(qu.x), q23 = unpack_bf2(qu.y);

    float4 acc = make_float4(0.f, 0.f, 0.f, 0.f);
    float den = 0.f;
    int beg = g_rowptr[node], end = g_rowptr[node + 1];

    int e = beg;
    for (; e + 1 < end; e += 2) {
        int s0 = g_csr_src[e], s1 = g_csr_src[e + 1];
        uint2 ku0 = kp[(size_t)s0 * 32 + lane];
        uint2 vu0 = vp[(size_t)s0 * 32 + lane];
        uint2 ku1 = kp[(size_t)s1 * 32 + lane];
        uint2 vu1 = vp[(size_t)s1 * 32 + lane];
        float2 ka0 = unpack_bf2(ku0.x), kb0 = unpack_bf2(ku0.y);
        float2 ka1 = unpack_bf2(ku1.x), kb1 = unpack_bf2(ku1.y);
        float d0 = q01.x * ka0.x + q01.y * ka0.y + q23.x * kb0.x + q23.y * kb0.y;
        float d1 = q01.x * ka1.x + q01.y * ka1.y + q23.x * kb1.x + q23.y * kb1.y;
        d0 += __shfl_xor_sync(0xffffffffu, d0, 1);
        d1 += __shfl_xor_sync(0xffffffffu, d1, 1);
        d0 += __shfl_xor_sync(0xffffffffu, d0, 2);
        d1 += __shfl_xor_sync(0xffffffffu, d1, 2);
        d0 += __shfl_xor_sync(0xffffffffu, d0, 4);
        d1 += __shfl_xor_sync(0xffffffffu, d1, 4);
        float p0 = __expf(d0 * 0.17677669529663689f);
        float p1 = __expf(d1 * 0.17677669529663689f);
        den += p0 + p1;
        float2 va0 = unpack_bf2(vu0.x), vb0 = unpack_bf2(vu0.y);
        float2 va1 = unpack_bf2(vu1.x), vb1 = unpack_bf2(vu1.y);
        acc.x += p0 * va0.x + p1 * va1.x;
        acc.y += p0 * va0.y + p1 * va1.y;
        acc.z += p0 * vb0.x + p1 * vb1.x;
        acc.w += p0 * vb0.y + p1 * vb1.y;
    }
    if (e < end) {
        int s0 = g_csr_src[e];
        uint2 ku0 = kp[(size_t)s0 * 32 + lane];
        uint2 vu0 = vp[(size_t)s0 * 32 + lane];
        float2 ka0 = unpack_bf2(ku0.x), kb0 = unpack_bf2(ku0.y);
        float d0 = q01.x * ka0.x + q01.y * ka0.y + q23.x * kb0.x + q23.y * kb0.y;
        d0 += __shfl_xor_sync(0xffffffffu, d0, 1);
        d0 += __shfl_xor_sync(0xffffffffu, d0, 2);
        d0 += __shfl_xor_sync(0xffffffffu, d0, 4);
        float p0 = __expf(d0 * 0.17677669529663689f);
        den += p0;
        float2 va0 = unpack_bf2(vu0.x), vb0 = unpack_bf2(vu0.y);
        acc.x += p0 * va0.x; acc.y += p0 * va0.y;
        acc.z += p0 * vb0.x; acc.w += p0 * vb0.y;
    }

    float inv = (den > 0.f) ? (1.f / den) : 0.f;
    float4 sk = *(const float4*)&skip[(size_t)node * 128 + lane * 4];
    float4 o = make_float4(fmaxf(sk.x + acc.x * inv, 0.f),
                           fmaxf(sk.y + acc.y * inv, 0.f),
                           fmaxf(sk.z + acc.z * inv, 0.f),
                           fmaxf(sk.w + acc.w * inv, 0.f));
    *(float4*)&h[(size_t)node * 128 + lane * 4] = o;
}

// ---------------- fused edge attention + partial colsum, layer 2 ----------
__global__ void edge_attn2(const unsigned* __restrict__ q,
                           const unsigned* __restrict__ k,
                           const unsigned* __restrict__ v,
                           const float* __restrict__ skip,
                           float* __restrict__ part, int n)
{
    __shared__ float cs[32];
    int tid = blockIdx.x * blockDim.x + threadIdx.x;
    int node = tid >> 3;
    int m = threadIdx.x & 7;
    unsigned gmask = 0xFFu << ((threadIdx.x & 31) & ~7);
    bool valid = node < n;

    const uint2* qp = (const uint2*)q;
    const uint2* kp = (const uint2*)k;
    const uint2* vp = (const uint2*)v;

    float2 q01 = make_float2(0.f, 0.f), q23 = make_float2(0.f, 0.f);
    int beg = 0, end = 0;
    if (valid) {
        uint2 qu = qp[(size_t)node * 8 + m];
        q01 = unpack_bf2(qu.x); q23 = unpack_bf2(qu.y);
        beg = g_rowptr[node]; end = g_rowptr[node + 1];
    }

    float4 acc = make_float4(0.f, 0.f, 0.f, 0.f);
    float den = 0.f;
    int e = beg;
    for (; e + 1 < end; e += 2) {
        int s0 = g_csr_src[e], s1 = g_csr_src[e + 1];
        uint2 ku0 = kp[(size_t)s0 * 8 + m];
        uint2 vu0 = vp[(size_t)s0 * 8 + m];
        uint2 ku1 = kp[(size_t)s1 * 8 + m];
        uint2 vu1 = vp[(size_t)s1 * 8 + m];
        float2 ka0 = unpack_bf2(ku0.x), kb0 = unpack_bf2(ku0.y);
        float2 ka1 = unpack_bf2(ku1.x), kb1 = unpack_bf2(ku1.y);
        float d0 = q01.x * ka0.x + q01.y * ka0.y + q23.x * kb0.x + q23.y * kb0.y;
        float d1 = q01.x * ka1.x + q01.y * ka1.y + q23.x * kb1.x + q23.y * kb1.y;
        d0 += __shfl_xor_sync(gmask, d0, 1);
        d1 += __shfl_xor_sync(gmask, d1, 1);
        d0 += __shfl_xor_sync(gmask, d0, 2);
        d1 += __shfl_xor_sync(gmask, d1, 2);
        d0 += __shfl_xor_sync(gmask, d0, 4);
        d1 += __shfl_xor_sync(gmask, d1, 4);
        float p0 = __expf(d0 * 0.17677669529663689f);
        float p1 = __expf(d1 * 0.17677669529663689f);
        den += p0 + p1;
        float2 va0 = unpack_bf2(vu0.x), vb0 = unpack_bf2(vu0.y);
        float2 va1 = unpack_bf2(vu1.x), vb1 = unpack_bf2(vu1.y);
        acc.x += p0 * va0.x + p1 * va1.x;
        acc.y += p0 * va0.y + p1 * va1.y;
        acc.z += p0 * vb0.x + p1 * vb1.x;
        acc.w += p0 * vb0.y + p1 * vb1.y;
    }
    if (e < end) {
        int s0 = g_csr_src[e];
        uint2 ku0 = kp[(size_t)s0 * 8 + m];
        uint2 vu0 = vp[(size_t)s0 * 8 + m];
        float2 ka0 = unpack_bf2(ku0.x), kb0 = unpack_bf2(ku0.y);
        float d0 = q01.x * ka0.x + q01.y * ka0.y + q23.x * kb0.x + q23.y * kb0.y;
        d0 += __shfl_xor_sync(gmask, d0, 1);
        d0 += __shfl_xor_sync(gmask, d0, 2);
        d0 += __shfl_xor_sync(gmask, d0, 4);
        float p0 = __expf(d0 * 0.17677669529663689f);
        den += p0;
        float2 va0 = unpack_bf2(vu0.x), vb0 = unpack_bf2(vu0.y);
        acc.x += p0 * va0.x; acc.y += p0 * va0.y;
        acc.z += p0 * vb0.x; acc.w += p0 * vb0.y;
    }

    float o0 = 0.f, o1 = 0.f, o2 = 0.f, o3 = 0.f;
    if (valid) {
        float inv = (den > 0.f) ? (1.f / den) : 0.f;
        float4 sk = *(const float4*)&skip[(size_t)node * 32 + m * 4];
        o0 = fmaxf(sk.x + acc.x * inv, 0.f);
        o1 = fmaxf(sk.y + acc.y * inv, 0.f);
        o2 = fmaxf(sk.z + acc.z * inv, 0.f);
        o3 = fmaxf(sk.w + acc.w * inv, 0.f);
    }

    o0 += __shfl_xor_sync(0xffffffffu, o0, 8);
    o1 += __shfl_xor_sync(0xffffffffu, o1, 8);
    o2 += __shfl_xor_sync(0xffffffffu, o2, 8);
    o3 += __shfl_xor_sync(0xffffffffu, o3, 8);
    o0 += __shfl_xor_sync(0xffffffffu, o0, 16);
    o1 += __shfl_xor_sync(0xffffffffu, o1, 16);
    o2 += __shfl_xor_sync(0xffffffffu, o2, 16);
    o3 += __shfl_xor_sync(0xffffffffu, o3, 16);

    if (threadIdx.x < 32) cs[threadIdx.x] = 0.f;
    __syncthreads();
    if ((threadIdx.x & 31) < 8) {
        atomicAdd(&cs[m * 4 + 0], o0);
        atomicAdd(&cs[m * 4 + 1], o1);
        atomicAdd(&cs[m * 4 + 2], o2);
        atomicAdd(&cs[m * 4 + 3], o3);
    }
    __syncthreads();
    if (threadIdx.x < 32) part[(size_t)blockIdx.x * 32 + threadIdx.x] = cs[threadIdx.x];
}

// ---------------- final: reduce partials, dot with Wo ----------------
__global__ void final_kernel(const float* __restrict__ Wo,
                             const float* __restrict__ bo,
                             float* __restrict__ out, int n, int nb2) {
    __shared__ float cs[32];
    int t = threadIdx.x;
    if (t < 32) cs[t] = 0.f;
    __syncthreads();
    int dim = t & 31, rs = t >> 5;
    float acc = 0.f;
    for (int r = rs; r < nb2; r += 32)
        acc += g_part[(size_t)r * 32 + dim];
    atomicAdd(&cs[dim], acc);
    __syncthreads();
    if (t < 32) {
        float val = (cs[t] / (float)n) * Wo[t];
        #pragma unroll
        for (int o = 16; o; o >>= 1) val += __shfl_down_sync(0xffffffffu, val, o);
        if (t == 0) out[0] = val + bo[0];
    }
}

// ---------------- launch ----------------
extern "C" void kernel_launch(void* const* d_in, const int* in_sizes, int n_in,
                              void* d_out, int out_size) {
    const float* x   = (const float*)d_in[0];
    const void*  ei  = d_in[1];
    const float* Wq1 = (const float*)d_in[2];  const float* bq1 = (const float*)d_in[3];
    const float* Wk1 = (const float*)d_in[4];  const float* bk1 = (const float*)d_in[5];
    const float* Wv1 = (const float*)d_in[6];  const float* bv1 = (const float*)d_in[7];
    const float* Ws1 = (const float*)d_in[8];  const float* bs1 = (const float*)d_in[9];
    const float* Wq2 = (const float*)d_in[10]; const float* bq2 = (const float*)d_in[11];
    const float* Wk2 = (const float*)d_in[12]; const float* bk2 = (const float*)d_in[13];
    const float* Wv2 = (const float*)d_in[14]; const float* bv2 = (const float*)d_in[15];
    const float* Ws2 = (const float*)d_in[16]; const float* bs2 = (const float*)d_in[17];
    const float* Wo  = (const float*)d_in[18]; const float* bo  = (const float*)d_in[19];
    float* out = (float*)d_out;

    int n = in_sizes[0] / 128;
    int E = in_sizes[1] / 2;
    if (n > MAX_NODES) n = MAX_NODES;
    if (E > MAX_EDGES) E = MAX_EDGES;

    unsigned *q1b, *k1b, *v1b, *q2b, *k2b, *v2b;
    float *s1, *h1, *s2, *part;
    cudaGetSymbolAddress((void**)&q1b, g_q1b);
    cudaGetSymbolAddress((void**)&k1b, g_k1b);
    cudaGetSymbolAddress((void**)&v1b, g_v1b);
    cudaGetSymbolAddress((void**)&s1,  g_s1);
    cudaGetSymbolAddress((void**)&h1,  g_h1);
    cudaGetSymbolAddress((void**)&q2b, g_q2b);
    cudaGetSymbolAddress((void**)&k2b, g_k2b);
    cudaGetSymbolAddress((void**)&v2b, g_v2b);
    cudaGetSymbolAddress((void**)&s2,  g_s2);
    cudaGetSymbolAddress((void**)&part, g_part);

    const int SMEM = (128 * SA + 64 * SB) * (int)sizeof(float);   // 102400 B
    cudaFuncSetAttribute(gemm_l1, cudaFuncAttributeMaxDynamicSharedMemorySize, SMEM);
    cudaFuncSetAttribute(gemm_l2, cudaFuncAttributeMaxDynamicSharedMemorySize, SMEM);

    init_kernel<<<(n + 256) / 256, 256>>>((const int*)ei, n);
    unpack_hist_kernel<<<(E + 255) / 256, 256>>>(ei, E);
    int nb = (n + 2047) / 2048;
    scan_phase1<<<nb, 256>>>(n);
    scan_phase2<<<1, 32>>>(nb, n);
    scan_phase3<<<(n + 255) / 256, 256>>>(n);
    fill_kernel<<<(E + 255) / 256, 256>>>(E);

    int gb = (n + 127) / 128;
    gemm_l1<<<gb, 256, SMEM>>>(x, Wq1, Wk1, Wv1, Ws1, bq1, bk1, bv1, bs1,
                               q1b, k1b, v1b, s1, n);
    edge_attn1<<<(n * 32 + 255) / 256, 256>>>(q1b, k1b, v1b, s1, h1, n);

    gemm_l2<<<gb, 256, SMEM>>>(h1, Wq2, Wk2, Wv2, Ws2, bq2, bk2, bv2, bs2,
                               q2b, k2b, v2b, s2, n);
    int nb2 = (n + 31) / 32;
    edge_attn2<<<nb2, 256>>>(q2b, k2b, v2b, s2, part, n);

    final_kernel<<<1, 1024>>>(Wo, bo, out, n, nb2);
}